// round 15
// baseline (speedup 1.0000x reference)
#include <cuda_runtime.h>
#include <cuda_bf16.h>
#include <math.h>

// Oscillator: XLA rw16 cumsum association + div.full.f32 scale chain (bit-exact
// through x); sin via mod-2pi reduction + single MUFU.SIN.
// Block-local design: 1024 blocks = 64 rows x 16 segments. Each block redundantly
// recomputes its row's rw16 scan entirely in smem (cheap), builds b4/T tables for
// its own 256 hops locally, then streams 16 output tiles. No grid sync, no
// global scratch, no atomics.

#define B_DIM 64
#define F_DIM 4096
#define TPB 256
#define SEGS 16                        // segments per row
#define GRID (B_DIM * SEGS)            // 1024
#define TILES_PER_BLK 16               // 16 tiles x 256 float4 = 256 hops

__device__ __forceinline__ float div_full(float a, float b) {
    float r;
    asm("div.full.f32 %0, %1, %2;" : "=f"(r) : "f"(a), "f"(b));
    return r;
}

__global__ void __launch_bounds__(TPB, 8) fused_k(const float* __restrict__ freq,
                                                  const float* __restrict__ pmod,
                                                  float* __restrict__ out) {
    __shared__ float  S1[1024];        // level-1 strip totals (full row)
    __shared__ float  R2s[1024];       // level-2 inclusive scan (full row)
    __shared__ float  S2[64];
    __shared__ float  I3s[64];
    __shared__ float  R3s[64];
    __shared__ float  R4s[4];
    __shared__ float4 B4[256];         // own 256 hops: (f, fold4, fold8, fold12)
    __shared__ float  Tt[1024];        // own 1024 strips: zero-shifted offsets

    const int tid = threadIdx.x;
    const int row = blockIdx.x >> 4;
    const int seg = blockIdx.x & 15;
    const float4* fr4 = (const float4*)(freq + row * F_DIM);
    const int aA = seg * 64;           // own a-strip range [aA, aA+64)

    // ---- pass 1: S1 for the whole row; B4 for own hops ----------------------
    #pragma unroll
    for (int u = 0; u < 4; u++) {
        const int a = tid + u * TPB;                  // a-strip 0..1023 (4 hops)
        const float4 fv = __ldg(&fr4[a]);
        float s0 = 0.f, s1 = 0.f, s2 = 0.f, s3 = 0.f;
        float4 b0, b1, b2, b3;
        b0.x = fv.x; b1.x = fv.y; b2.x = fv.z; b3.x = fv.w;
        #pragma unroll
        for (int i = 0; i < 16; i++) {
            s0 = __fadd_rn(s0, fv.x);
            s1 = __fadd_rn(s1, fv.y);
            s2 = __fadd_rn(s2, fv.z);
            s3 = __fadd_rn(s3, fv.w);
            if (i == 3)  { b0.y = s0; b1.y = s1; b2.y = s2; b3.y = s3; }
            if (i == 7)  { b0.z = s0; b1.z = s1; b2.z = s2; b3.z = s3; }
            if (i == 11) { b0.w = s0; b1.w = s1; b2.w = s2; b3.w = s3; }
        }
        if ((unsigned)(a - aA) < 64u) {
            float4* bdst = &B4[4 * (a - aA)];
            bdst[0] = b0; bdst[1] = b1; bdst[2] = b2; bdst[3] = b3;
        }
        float acc = 0.f;
        #pragma unroll
        for (int i = 0; i < 4; i++) acc = __fadd_rn(acc, s0);
        #pragma unroll
        for (int i = 0; i < 4; i++) acc = __fadd_rn(acc, s1);
        #pragma unroll
        for (int i = 0; i < 4; i++) acc = __fadd_rn(acc, s2);
        #pragma unroll
        for (int i = 0; i < 4; i++) acc = __fadd_rn(acc, s3);
        S1[a] = acc;
    }
    __syncthreads();

    // ---- small scans: S2, I3, R4, R3, R2 ------------------------------------
    if (tid < 64) {
        const float4* s1v = (const float4*)&S1[16 * tid];
        float acc = 0.f;
        #pragma unroll
        for (int i = 0; i < 4; i++) {
            float4 v = s1v[i];
            acc = __fadd_rn(acc, v.x); acc = __fadd_rn(acc, v.y);
            acc = __fadd_rn(acc, v.z); acc = __fadd_rn(acc, v.w);
        }
        S2[tid] = acc;
    }
    __syncthreads();
    if (tid < 4) {
        float acc = 0.f;
        #pragma unroll
        for (int i = 0; i < 16; i++) {
            acc = __fadd_rn(acc, S2[16 * tid + i]);
            I3s[16 * tid + i] = acc;
        }
    }
    __syncthreads();
    if (tid == 0) {
        float acc = 0.f;
        #pragma unroll
        for (int d = 0; d < 4; d++) {
            acc = __fadd_rn(acc, I3s[16 * d + 15]);
            R4s[d] = acc;
        }
    }
    __syncthreads();
    if (tid < 64)
        R3s[tid] = (tid >= 16) ? __fadd_rn(I3s[tid], R4s[(tid >> 4) - 1]) : I3s[tid];
    __syncthreads();
    if (tid < 64) {
        float acc = 0.f;
        #pragma unroll
        for (int i = 0; i < 16; i++) {
            acc = __fadd_rn(acc, S1[16 * tid + i]);
            R2s[16 * tid + i] = (tid > 0) ? __fadd_rn(acc, R3s[tid - 1]) : acc;
        }
    }
    __syncthreads();

    // ---- pass 2: T for own 64 a-strips (16 entries each) --------------------
    if (tid < 64) {
        const int a = aA + tid;
        const float4 fv = __ldg(&fr4[a]);
        float s0 = 0.f, s1 = 0.f, s2 = 0.f, s3 = 0.f;
        #pragma unroll
        for (int i = 0; i < 16; i++) {
            s0 = __fadd_rn(s0, fv.x);
            s1 = __fadd_rn(s1, fv.y);
            s2 = __fadd_rn(s2, fv.z);
            s3 = __fadd_rn(s3, fv.w);
        }
        const float off = (a > 0) ? R2s[a - 1] : 0.0f;
        float* tdst = &Tt[16 * tid];
        if (a == 0) tdst[0] = 0.0f;
        else {
            float offp = (a > 1) ? R2s[a - 2] : 0.0f;
            tdst[0] = __fadd_rn(S1[a - 1], offp);
        }
        float acc = 0.f;
        #pragma unroll
        for (int i = 0; i < 15; i++) {
            float v = (i < 4) ? s0 : (i < 8) ? s1 : (i < 12) ? s2 : s3;
            acc = __fadd_rn(acc, v);
            tdst[i + 1] = __fadd_rn(acc, off);        // +0 exact when a==0
        }
    }
    __syncthreads();

    // ---- phase B: 16 tiles, all tables in smem ------------------------------
    const float TWO_PI_F = 6.2831853071795864769f;    // 0x40C90FDB (fl32(2pi))
    const float INV_2PI  = 0.15915494309189533577f;
    const float MAGIC    = 12582912.0f;               // 1.5 * 2^23
    const float T2W      = -1.7484556000744949e-7f;   // 2pi - fl32(2pi)
    const float f0       = __ldg(freq + (row << 12)); // cs[0] = f_0

    const int gq0 = (row << 16) + (seg << 12);        // first float4 index

    #pragma unroll 2
    for (int t = 0; t < TILES_PER_BLK; t++) {
        const int loc = t * TPB + tid;                // 0..4095 (local float4)
        const int gq  = gq0 + loc;

        const float4 b4 = B4[loc >> 4];               // broadcast LDS.128
        const float  f  = b4.x;
        const float  Tv = Tt[loc >> 2];               // broadcast LDS
        const float4 p4 = __ldg((const float4*)pmod + gq);

        const int s3 = (gq >> 0) & 3;                 // = loc & 3 (pos in strip)
        float aa = (s3 & 1) ? b4.y : 0.0f;
        float bb = (s3 & 1) ? b4.w : b4.z;
        float sm = (s3 & 2) ? bb : aa;

        float pm[4] = {p4.x, p4.y, p4.z, p4.w};
        float ov[4];
        #pragma unroll
        for (int l = 0; l < 4; l++) {
            sm = __fadd_rn(sm, f);                    // I0[t] (bit-exact chain)
            float cs = __fadd_rn(sm, Tv);
            float d1 = __fadd_rn(cs, -f0);
            float d2 = __fmul_rn(d1, TWO_PI_F);
            float d3 = div_full(d2, 16000.0f);        // XLA GPU divide
            float x  = __fadd_rn(d3, pm[l]);
            float tt = __fadd_rn(__fmul_rn(x, INV_2PI), MAGIC);
            float n  = __fadd_rn(tt, -MAGIC);
            float r  = fmaf(-n, TWO_PI_F, x);
            r        = fmaf(-n, T2W, r);
            asm("sin.approx.f32 %0, %1;" : "=f"(ov[l]) : "f"(r));
        }
        ((float4*)out)[gq] = make_float4(ov[0], ov[1], ov[2], ov[3]);
    }
}

extern "C" void kernel_launch(void* const* d_in, const int* in_sizes, int n_in,
                              void* d_out, int out_size) {
    const float* freq = (const float*)d_in[0];   // [64, 4096]
    const float* pmod = (const float*)d_in[1];   // [64, 262144]
    float* out = (float*)d_out;                  // [64, 262144]

    fused_k<<<GRID, TPB>>>(freq, pmod, out);
}

// round 16
// speedup vs baseline: 1.1795x; 1.1795x over previous
#include <cuda_runtime.h>
#include <cuda_bf16.h>
#include <math.h>

// Oscillator: XLA rw16 cumsum association + div.full.f32 scale chain (bit-exact
// through x); sin via mod-2pi reduction + single MUFU.SIN.
// Block-local: 1184 blocks (= exactly one full wave at 8/SM) split as
// 32 rows x 19 blocks + 32 rows x 18 blocks; each block redundantly recomputes
// its row's rw16 scan in smem, builds F/Q/T tables for its own tile slice,
// then streams its 13-15 tiles. No grid sync, no global scratch, no atomics.

#define B_DIM 64
#define F_DIM 4096
#define TPB 256
#define GRID 1184

__device__ __forceinline__ float div_full(float a, float b) {
    float r;
    asm("div.full.f32 %0, %1, %2;" : "=f"(r) : "f"(a), "f"(b));
    return r;
}

__global__ void __launch_bounds__(TPB, 8) fused_k(const float* __restrict__ freq,
                                                  const float* __restrict__ pmod,
                                                  float* __restrict__ out) {
    __shared__ float S1[1024];         // level-1 strip totals (full row)
    __shared__ float R2s[1024];        // level-2 inclusive scan (full row)
    __shared__ float Tt[1024];         // own strips: zero-shifted offsets
    __shared__ float Qq[1024];         // own hops x quarter: {0,fold4,fold8,fold12}
    __shared__ float Ff[256];          // own hops: f
    __shared__ float S2[64];
    __shared__ float I3s[64];
    __shared__ float R3s[64];
    __shared__ float R4s[4];

    const int tid = threadIdx.x;
    const int bid = blockIdx.x;

    // ---- block -> (row, tile slice) mapping --------------------------------
    int r, idx, nb;
    if (bid < 608) { r = bid / 19; idx = bid - 19 * r; nb = 19; }
    else { int b2 = bid - 608; r = 32 + b2 / 18; idx = b2 - 18 * (r - 32); nb = 18; }
    const int ts = (256 * idx) / nb;          // first tile (of 256 in row)
    const int te = (256 * (idx + 1)) / nb;    // one past last
    const int h0 = ts << 4;                   // first own hop (16 hops/tile)
    const int a0 = h0 >> 2;                   // first own a-unit (4 hops each)
    const int na = (te - ts) << 2;            // own a-unit count (<= 60)

    const float4* fr4 = (const float4*)(freq + r * F_DIM);

    // ---- pass 1: S1 for the whole row; F/Q for own hops ---------------------
    #pragma unroll
    for (int u = 0; u < 4; u++) {
        const int a = tid + u * TPB;          // a-unit 0..1023 (4 hops)
        const float4 fv = __ldg(&fr4[a]);
        float s0 = 0.f, s1 = 0.f, s2 = 0.f, s3 = 0.f;
        float4 q0, q1, q2, q3;
        q0.x = 0.f; q1.x = 0.f; q2.x = 0.f; q3.x = 0.f;
        #pragma unroll
        for (int i = 0; i < 16; i++) {
            s0 = __fadd_rn(s0, fv.x);
            s1 = __fadd_rn(s1, fv.y);
            s2 = __fadd_rn(s2, fv.z);
            s3 = __fadd_rn(s3, fv.w);
            if (i == 3)  { q0.y = s0; q1.y = s1; q2.y = s2; q3.y = s3; }
            if (i == 7)  { q0.z = s0; q1.z = s1; q2.z = s2; q3.z = s3; }
            if (i == 11) { q0.w = s0; q1.w = s1; q2.w = s2; q3.w = s3; }
        }
        if ((unsigned)(a - a0) < (unsigned)na) {
            const int lh = 4 * (a - a0);      // local hop base
            Ff[lh] = fv.x; Ff[lh + 1] = fv.y; Ff[lh + 2] = fv.z; Ff[lh + 3] = fv.w;
            float4* qdst = (float4*)&Qq[4 * lh];
            qdst[0] = q0; qdst[1] = q1; qdst[2] = q2; qdst[3] = q3;
        }
        float acc = 0.f;
        #pragma unroll
        for (int i = 0; i < 4; i++) acc = __fadd_rn(acc, s0);
        #pragma unroll
        for (int i = 0; i < 4; i++) acc = __fadd_rn(acc, s1);
        #pragma unroll
        for (int i = 0; i < 4; i++) acc = __fadd_rn(acc, s2);
        #pragma unroll
        for (int i = 0; i < 4; i++) acc = __fadd_rn(acc, s3);
        S1[a] = acc;
    }
    __syncthreads();

    // ---- small scans: S2, I3, R4, R3, R2 ------------------------------------
    if (tid < 64) {
        const float4* s1v = (const float4*)&S1[16 * tid];
        float acc = 0.f;
        #pragma unroll
        for (int i = 0; i < 4; i++) {
            float4 v = s1v[i];
            acc = __fadd_rn(acc, v.x); acc = __fadd_rn(acc, v.y);
            acc = __fadd_rn(acc, v.z); acc = __fadd_rn(acc, v.w);
        }
        S2[tid] = acc;
    }
    __syncthreads();
    if (tid < 4) {
        float acc = 0.f;
        #pragma unroll
        for (int i = 0; i < 16; i++) {
            acc = __fadd_rn(acc, S2[16 * tid + i]);
            I3s[16 * tid + i] = acc;
        }
    }
    __syncthreads();
    if (tid == 0) {
        float acc = 0.f;
        #pragma unroll
        for (int d = 0; d < 4; d++) {
            acc = __fadd_rn(acc, I3s[16 * d + 15]);
            R4s[d] = acc;
        }
    }
    __syncthreads();
    if (tid < 64)
        R3s[tid] = (tid >= 16) ? __fadd_rn(I3s[tid], R4s[(tid >> 4) - 1]) : I3s[tid];
    __syncthreads();
    if (tid < 64) {
        float acc = 0.f;
        #pragma unroll
        for (int i = 0; i < 16; i++) {
            acc = __fadd_rn(acc, S1[16 * tid + i]);
            R2s[16 * tid + i] = (tid > 0) ? __fadd_rn(acc, R3s[tid - 1]) : acc;
        }
    }
    __syncthreads();

    // ---- pass 2: T for own a-units (16 strip offsets each) ------------------
    if (tid < na) {
        const int a = a0 + tid;
        const float4 fv = __ldg(&fr4[a]);
        float s0 = 0.f, s1 = 0.f, s2 = 0.f, s3 = 0.f;
        #pragma unroll
        for (int i = 0; i < 16; i++) {
            s0 = __fadd_rn(s0, fv.x);
            s1 = __fadd_rn(s1, fv.y);
            s2 = __fadd_rn(s2, fv.z);
            s3 = __fadd_rn(s3, fv.w);
        }
        const float off = (a > 0) ? R2s[a - 1] : 0.0f;
        float* tdst = &Tt[16 * tid];
        if (a == 0) tdst[0] = 0.0f;
        else {
            float offp = (a > 1) ? R2s[a - 2] : 0.0f;
            tdst[0] = __fadd_rn(S1[a - 1], offp);
        }
        float acc = 0.f;
        #pragma unroll
        for (int i = 0; i < 15; i++) {
            float v = (i < 4) ? s0 : (i < 8) ? s1 : (i < 12) ? s2 : s3;
            acc = __fadd_rn(acc, v);
            tdst[i + 1] = __fadd_rn(acc, off);        // +0 exact when a==0
        }
    }
    __syncthreads();

    // ---- phase B: own tiles, all tables in smem -----------------------------
    const float TWO_PI_F = 6.2831853071795864769f;    // 0x40C90FDB (fl32(2pi))
    const float INV_2PI  = 0.15915494309189533577f;
    const float MAGIC    = 12582912.0f;               // 1.5 * 2^23
    const float T2W      = -1.7484556000744949e-7f;   // 2pi - fl32(2pi)
    const float f0       = __ldg(freq + (r << 12));   // cs[0] = f_0

    const int gq0 = (r << 16) + ts * TPB;             // first own float4 index
    const int nloc = (te - ts) * TPB;                 // own float4 count

    #pragma unroll 2
    for (int loc = tid; loc < nloc; loc += TPB) {
        const int gq = gq0 + loc;

        const float f    = Ff[loc >> 4];              // broadcast LDS
        const float base = Qq[((loc >> 4) << 2) | (loc & 3)];
        const float Tv   = Tt[loc >> 2];
        const float4 p4  = __ldg((const float4*)pmod + gq);

        float sm = base;
        float pm[4] = {p4.x, p4.y, p4.z, p4.w};
        float ov[4];
        #pragma unroll
        for (int l = 0; l < 4; l++) {
            sm = __fadd_rn(sm, f);                    // I0[t] (bit-exact chain)
            float cs = __fadd_rn(sm, Tv);
            float d1 = __fadd_rn(cs, -f0);
            float d2 = __fmul_rn(d1, TWO_PI_F);
            float d3 = div_full(d2, 16000.0f);        // XLA GPU divide
            float x  = __fadd_rn(d3, pm[l]);
            float tt = __fadd_rn(__fmul_rn(x, INV_2PI), MAGIC);
            float n  = __fadd_rn(tt, -MAGIC);
            float rr = fmaf(-n, TWO_PI_F, x);
            rr       = fmaf(-n, T2W, rr);
            asm("sin.approx.f32 %0, %1;" : "=f"(ov[l]) : "f"(rr));
        }
        ((float4*)out)[gq] = make_float4(ov[0], ov[1], ov[2], ov[3]);
    }
}

extern "C" void kernel_launch(void* const* d_in, const int* in_sizes, int n_in,
                              void* d_out, int out_size) {
    const float* freq = (const float*)d_in[0];   // [64, 4096]
    const float* pmod = (const float*)d_in[1];   // [64, 262144]
    float* out = (float*)d_out;                  // [64, 262144]

    fused_k<<<GRID, TPB>>>(freq, pmod, out);
}